// round 1
// baseline (speedup 1.0000x reference)
#include <cuda_runtime.h>
#include <cuda_bf16.h>

// Problem constants
#define Bb   256
#define Ssz  1000
#define Esz  512
#define Hh   8
#define DHsz 64
#define DFFsz 2048

// Scratch (device globals: allocation-free)
__device__ float g_glimpse[Bb * Esz];   // attention output + residual
__device__ float g_T[Bb * DFFsz];       // FFN hidden
__device__ float g_G2[Bb * Esz];        // FFN output + residual

#define NEG_BIG (-1e30f)

// ---------------------------------------------------------------------------
// Kernel 1: per-batch multi-head attention -> glimpse = heads + query
// 1 CTA per batch, 1024 threads (32 warps).
// ---------------------------------------------------------------------------
__global__ __launch_bounds__(1024) void attn_kernel(
    const float* __restrict__ q,     // [B, E]  (L=1)
    const float* __restrict__ kk,    // [B, S, E]
    const float* __restrict__ vv,    // [B, S, E]
    const int*   __restrict__ mask,  // [B, S] nonzero = attend
    float* __restrict__ glimpse)     // [B, E]
{
    __shared__ float qs[Esz];
    __shared__ float sc[Hh * Ssz];     // scores -> probs (32 KB)
    __shared__ float heads_s[Esz];
    __shared__ float red[Hh * 4];
    __shared__ float inv_sum[Hh];

    const int b    = blockIdx.x;
    const int tid  = threadIdx.x;
    const int wid  = tid >> 5;
    const int lane = tid & 31;

    if (tid < Esz) {
        qs[tid] = q[b * Esz + tid];
        heads_s[tid] = 0.f;
    }
    __syncthreads();

    const float4* qv4 = (const float4*)qs;
    const float* kb = kk + (size_t)b * Ssz * Esz;
    const float* vb = vv + (size_t)b * Ssz * Esz;
    const int*   mb = mask + b * Ssz;

    // ---- Pass A: scores[h][s] = (q_h . k_{s,h}) / 8, masked ----
    for (int s = wid; s < Ssz; s += 32) {
        const float4* krow = (const float4*)(kb + (size_t)s * Esz);
        const bool mm = (mb[s] != 0);
        #pragma unroll
        for (int j = 0; j < 4; j++) {
            // instruction j covers elements [j*128, j*128+128) of the row,
            // fully coalesced 512B. Lane's 4 floats lie in head 2j + (lane>>4).
            float4 kv = krow[j * 32 + lane];
            float4 qq = qv4[j * 32 + lane];
            float p = kv.x * qq.x + kv.y * qq.y + kv.z * qq.z + kv.w * qq.w;
            p += __shfl_xor_sync(0xffffffffu, p, 1);
            p += __shfl_xor_sync(0xffffffffu, p, 2);
            p += __shfl_xor_sync(0xffffffffu, p, 4);
            p += __shfl_xor_sync(0xffffffffu, p, 8);
            if ((lane & 15) == 0) {
                int h = 2 * j + (lane >> 4);
                sc[h * Ssz + s] = mm ? p * 0.125f : NEG_BIG;
            }
        }
    }
    __syncthreads();

    // ---- Softmax per head: 4 warps (128 threads) per head ----
    {
        const int h = wid >> 2;
        const int sub = wid & 3;
        const int t128 = sub * 32 + lane;

        float m = NEG_BIG;
        for (int s = t128; s < Ssz; s += 128) m = fmaxf(m, sc[h * Ssz + s]);
        #pragma unroll
        for (int o = 16; o; o >>= 1) m = fmaxf(m, __shfl_xor_sync(0xffffffffu, m, o));
        if (lane == 0) red[h * 4 + sub] = m;
        __syncthreads();
        m = fmaxf(fmaxf(red[h * 4 + 0], red[h * 4 + 1]),
                  fmaxf(red[h * 4 + 2], red[h * 4 + 3]));
        __syncthreads();   // protect red[] before reuse

        float sum = 0.f;
        for (int s = t128; s < Ssz; s += 128) {
            float e = __expf(sc[h * Ssz + s] - m);  // masked -> ~0
            sc[h * Ssz + s] = e;
            sum += e;
        }
        #pragma unroll
        for (int o = 16; o; o >>= 1) sum += __shfl_xor_sync(0xffffffffu, sum, o);
        if (lane == 0) red[h * 4 + sub] = sum;
        __syncthreads();
        if (t128 == 0) {
            float tot = red[h * 4 + 0] + red[h * 4 + 1] + red[h * 4 + 2] + red[h * 4 + 3];
            inv_sum[h] = 1.0f / tot;
        }
    }
    __syncthreads();

    // ---- Pass B: heads[e] = sum_s p[h(e)][s] * v[s][e] ----
    {
        float acc[16];
        #pragma unroll
        for (int i = 0; i < 16; i++) acc[i] = 0.f;

        for (int s = wid; s < Ssz; s += 32) {
            const float4* vrow = (const float4*)(vb + (size_t)s * Esz);
            #pragma unroll
            for (int j = 0; j < 4; j++) {
                int h = 2 * j + (lane >> 4);
                float p = sc[h * Ssz + s];          // broadcast within 16 lanes
                float4 vx = vrow[j * 32 + lane];
                acc[4 * j + 0] += p * vx.x;
                acc[4 * j + 1] += p * vx.y;
                acc[4 * j + 2] += p * vx.z;
                acc[4 * j + 3] += p * vx.w;
            }
        }
        #pragma unroll
        for (int j = 0; j < 4; j++) {
            int h = 2 * j + (lane >> 4);
            float inv = inv_sum[h];
            int e = (j * 32 + lane) * 4;
            atomicAdd(&heads_s[e + 0], acc[4 * j + 0] * inv);
            atomicAdd(&heads_s[e + 1], acc[4 * j + 1] * inv);
            atomicAdd(&heads_s[e + 2], acc[4 * j + 2] * inv);
            atomicAdd(&heads_s[e + 3], acc[4 * j + 3] * inv);
        }
    }
    __syncthreads();

    if (tid < Esz) glimpse[b * Esz + tid] = heads_s[tid] + qs[tid];
}

// ---------------------------------------------------------------------------
// Generic tiled fp32 GEMM: C[M,N] = epilogue(A[M,K] @ B[K,N])
// EPI 0: relu(x + bias[n]);  EPI 1: x + bias[n] + resid[m*N+n]
// ---------------------------------------------------------------------------
template <int BM, int BN, int BK, int TM, int TN, int EPI>
__global__ __launch_bounds__(256) void gemm_kernel(
    const float* __restrict__ A, const float* __restrict__ B,
    float* __restrict__ C, const float* __restrict__ bias,
    const float* __restrict__ resid, int M, int N, int K)
{
    __shared__ float As[BM][BK + 1];
    __shared__ float Bs[BK][BN];

    constexpr int TX = BN / TN;
    const int tid = threadIdx.x;
    const int tx = tid % TX;
    const int ty = tid / TX;
    const int m0 = blockIdx.y * BM;
    const int n0 = blockIdx.x * BN;

    float acc[TM][TN];
    #pragma unroll
    for (int i = 0; i < TM; i++)
        #pragma unroll
        for (int j = 0; j < TN; j++) acc[i][j] = 0.f;

    for (int k0 = 0; k0 < K; k0 += BK) {
        for (int i = tid; i < BM * BK; i += 256) {
            int r = i / BK, c = i % BK;
            As[r][c] = A[(size_t)(m0 + r) * K + k0 + c];
        }
        for (int i = tid; i < BK * BN; i += 256) {
            int r = i / BN, c = i % BN;
            Bs[r][c] = B[(size_t)(k0 + r) * N + n0 + c];
        }
        __syncthreads();
        #pragma unroll
        for (int kkk = 0; kkk < BK; kkk++) {
            float ra[TM], rb[TN];
            #pragma unroll
            for (int i = 0; i < TM; i++) ra[i] = As[ty * TM + i][kkk];
            #pragma unroll
            for (int j = 0; j < TN; j++) rb[j] = Bs[kkk][tx * TN + j];
            #pragma unroll
            for (int i = 0; i < TM; i++)
                #pragma unroll
                for (int j = 0; j < TN; j++) acc[i][j] += ra[i] * rb[j];
        }
        __syncthreads();
    }

    #pragma unroll
    for (int i = 0; i < TM; i++) {
        int m = m0 + ty * TM + i;
        #pragma unroll
        for (int j = 0; j < TN; j++) {
            int n = n0 + tx * TN + j;
            float x = acc[i][j] + bias[n];
            if (EPI == 0) {
                x = fmaxf(x, 0.f);
            } else {
                x += resid[(size_t)m * N + n];
            }
            C[(size_t)m * N + n] = x;
        }
    }
}

// ---------------------------------------------------------------------------
// Kernel 3: logits[b][s] = dot(g2[b], logit_key[b][s]) / sqrt(E)
// grid (8 s-chunks, 256 batches), 1024 threads
// ---------------------------------------------------------------------------
__global__ __launch_bounds__(1024) void logits_kernel(
    const float* __restrict__ g2,    // [B, E]
    const float* __restrict__ lk,    // [B, S, E]
    float* __restrict__ out)         // [B, S]
{
    __shared__ float gs[Esz];
    const int b    = blockIdx.y;
    const int tid  = threadIdx.x;
    const int wid  = tid >> 5;
    const int lane = tid & 31;

    if (tid < Esz) gs[tid] = g2[b * Esz + tid];
    __syncthreads();

    const float4* g4 = (const float4*)gs;
    const int s0 = blockIdx.x * 125;
    const float rscale = 0.04419417382415922f;  // 1/sqrt(512)

    for (int i = wid; i < 125; i += 32) {
        int s = s0 + i;
        const float4* row = (const float4*)(lk + ((size_t)b * Ssz + s) * Esz);
        float p = 0.f;
        #pragma unroll
        for (int j = 0; j < 4; j++) {
            float4 a = row[j * 32 + lane];
            float4 qv = g4[j * 32 + lane];
            p += a.x * qv.x + a.y * qv.y + a.z * qv.z + a.w * qv.w;
        }
        #pragma unroll
        for (int o = 16; o; o >>= 1) p += __shfl_xor_sync(0xffffffffu, p, o);
        if (lane == 0) out[(size_t)b * Ssz + s] = p * rscale;
    }
}

// ---------------------------------------------------------------------------
// Launch
// ---------------------------------------------------------------------------
extern "C" void kernel_launch(void* const* d_in, const int* in_sizes, int n_in,
                              void* d_out, int out_size)
{
    const float* query    = (const float*)d_in[0];  // [B,1,E]
    const float* key      = (const float*)d_in[1];  // [B,S,E]
    const float* value    = (const float*)d_in[2];  // [B,S,E]
    const float* logitkey = (const float*)d_in[3];  // [B,S,E]
    const int*   mask     = (const int*)  d_in[4];  // [B,S]
    const float* W1       = (const float*)d_in[5];  // [E,DFF]
    const float* b1       = (const float*)d_in[6];  // [DFF]
    const float* W2       = (const float*)d_in[7];  // [DFF,E]
    const float* b2       = (const float*)d_in[8];  // [E]
    float* out            = (float*)d_out;          // [B,S]

    float *p_glimpse, *p_T, *p_G2;
    cudaGetSymbolAddress((void**)&p_glimpse, g_glimpse);
    cudaGetSymbolAddress((void**)&p_T, g_T);
    cudaGetSymbolAddress((void**)&p_G2, g_G2);

    attn_kernel<<<Bb, 1024>>>(query, key, value, mask, p_glimpse);

    // T = relu(G @ W1 + b1)   M=256, N=2048, K=512
    gemm_kernel<64, 64, 16, 4, 4, 0>
        <<<dim3(DFFsz / 64, Bb / 64), 256>>>(p_glimpse, W1, p_T, b1, nullptr,
                                             Bb, DFFsz, Esz);

    // G2 = T @ W2 + b2 + G    M=256, N=512, K=2048
    gemm_kernel<32, 32, 16, 2, 2, 1>
        <<<dim3(Esz / 32, Bb / 32), 256>>>(p_T, W2, p_G2, b2, p_glimpse,
                                           Bb, Esz, DFFsz);

    logits_kernel<<<dim3(8, Bb), 1024>>>(p_G2, logitkey, out);
}

// round 2
// speedup vs baseline: 1.9614x; 1.9614x over previous
#include <cuda_runtime.h>
#include <cuda_bf16.h>

#define Bb    256
#define Ssz   1000
#define Esz   512
#define Hh    8
#define DHsz  64
#define DFFsz 2048
#define NEG_BIG (-1e30f)

// Scratch (device globals: allocation-free)
__device__ float g_glimpse[Bb * Esz];
__device__ float g_T[Bb * DFFsz];
__device__ float g_G2[Bb * Esz];

// ---------------------------------------------------------------------------
// Kernel 1: attention. Grid (4 E-chunks, 256 batches), 256 threads (8 warps).
// Each CTA handles 2 heads (128 contiguous E columns) of one batch.
// ---------------------------------------------------------------------------
__global__ __launch_bounds__(256) void attn_kernel(
    const float* __restrict__ q,     // [B, E]
    const float* __restrict__ kk,    // [B, S, E]
    const float* __restrict__ vv,    // [B, S, E]
    const int*   __restrict__ mask,  // [B, S]
    float* __restrict__ glimpse)     // [B, E]
{
    __shared__ float qs[128];
    __shared__ float sc[2][Ssz];      // scores/probs for 2 heads (8 KB)
    __shared__ float wacc[8][128];    // per-warp V partials (4 KB)
    __shared__ float red[2][4];
    __shared__ float invs[2];

    const int hp   = blockIdx.x;      // 0..3
    const int b    = blockIdx.y;
    const int tid  = threadIdx.x;
    const int wid  = tid >> 5;
    const int lane = tid & 31;
    const int e0   = hp * 128;

    if (tid < 128) qs[tid] = q[b * Esz + e0 + tid];
    __syncthreads();

    const float4* q4 = (const float4*)qs;
    const float* kb = kk + (size_t)b * Ssz * Esz + e0;
    const float* vb = vv + (size_t)b * Ssz * Esz + e0;
    const int*   mb = mask + b * Ssz;

    // ---- Pass A: scores (2 rows per warp iteration for MLP) ----
    {
        const float4 qq = q4[lane];
        for (int s = wid * 2; s < Ssz; s += 16) {
            float4 k0 = ((const float4*)(kb + (size_t)s * Esz))[lane];
            float4 k1 = ((const float4*)(kb + (size_t)(s + 1) * Esz))[lane];
            int m0 = mb[s], m1 = mb[s + 1];
            float p0 = k0.x * qq.x + k0.y * qq.y + k0.z * qq.z + k0.w * qq.w;
            float p1 = k1.x * qq.x + k1.y * qq.y + k1.z * qq.z + k1.w * qq.w;
            #pragma unroll
            for (int o = 1; o < 16; o <<= 1) {
                p0 += __shfl_xor_sync(0xffffffffu, p0, o);
                p1 += __shfl_xor_sync(0xffffffffu, p1, o);
            }
            if ((lane & 15) == 0) {
                int h = lane >> 4;
                sc[h][s]     = m0 ? p0 * 0.125f : NEG_BIG;
                sc[h][s + 1] = m1 ? p1 * 0.125f : NEG_BIG;
            }
        }
    }
    __syncthreads();

    // ---- Softmax: 4 warps per head ----
    {
        const int h = wid >> 2;
        const int sub = wid & 3;
        const int t = sub * 32 + lane;

        float m = NEG_BIG;
        for (int s = t; s < Ssz; s += 128) m = fmaxf(m, sc[h][s]);
        #pragma unroll
        for (int o = 16; o; o >>= 1) m = fmaxf(m, __shfl_xor_sync(0xffffffffu, m, o));
        if (lane == 0) red[h][sub] = m;
        __syncthreads();
        m = fmaxf(fmaxf(red[h][0], red[h][1]), fmaxf(red[h][2], red[h][3]));
        __syncthreads();

        float sum = 0.f;
        for (int s = t; s < Ssz; s += 128) {
            float e = __expf(sc[h][s] - m);
            sc[h][s] = e;
            sum += e;
        }
        #pragma unroll
        for (int o = 16; o; o >>= 1) sum += __shfl_xor_sync(0xffffffffu, sum, o);
        if (lane == 0) red[h][sub] = sum;
        __syncthreads();
        if (t == 0)
            invs[h] = 1.0f / (red[h][0] + red[h][1] + red[h][2] + red[h][3]);
    }
    __syncthreads();

    // ---- Pass B: weighted V accumulation ----
    {
        const int h = lane >> 4;
        float a0 = 0.f, a1 = 0.f, a2 = 0.f, a3 = 0.f;
        for (int s = wid * 2; s < Ssz; s += 16) {
            float4 v0 = ((const float4*)(vb + (size_t)s * Esz))[lane];
            float4 v1 = ((const float4*)(vb + (size_t)(s + 1) * Esz))[lane];
            float p0 = sc[h][s];
            float p1 = sc[h][s + 1];
            a0 += p0 * v0.x + p1 * v1.x;
            a1 += p0 * v0.y + p1 * v1.y;
            a2 += p0 * v0.z + p1 * v1.z;
            a3 += p0 * v0.w + p1 * v1.w;
        }
        float inv = invs[h];
        ((float4*)wacc[wid])[lane] = make_float4(a0 * inv, a1 * inv, a2 * inv, a3 * inv);
    }
    __syncthreads();

    if (tid < 128) {
        float r = 0.f;
        #pragma unroll
        for (int w = 0; w < 8; w++) r += wacc[w][tid];
        glimpse[b * Esz + e0 + tid] = r + qs[tid];
    }
}

// ---------------------------------------------------------------------------
// Double-buffered fp32 GEMM. C[M,N] = epi(A[M,K] @ B[K,N])
// EPI 0: relu(x + bias);  EPI 1: x + bias + resid
// ---------------------------------------------------------------------------
template <int BM, int BN, int BK, int TM, int TN, int NT, int EPI>
__global__ __launch_bounds__(NT) void gemm_kernel(
    const float* __restrict__ A, const float* __restrict__ B,
    float* __restrict__ C, const float* __restrict__ bias,
    const float* __restrict__ resid, int M, int N, int K)
{
    constexpr int PAD = 4;
    __shared__ float As[2][BK][BM + PAD];   // A stored transposed [k][m]
    __shared__ float Bs[2][BK][BN];

    constexpr int TX = BN / TN;
    constexpr int KQ = BK / 4;
    constexpr int NQ = BN / 4;
    constexpr int AV = (BM * KQ) / NT;
    constexpr int BV = (BK * NQ) / NT;
    static_assert(AV * NT == BM * KQ && BV * NT == BK * NQ, "loader divisibility");
    static_assert(TX * (BM / TM) == NT, "thread tiling");

    const int tid = threadIdx.x;
    const int tx = tid % TX;
    const int ty = tid / TX;
    const int m0 = blockIdx.y * BM;
    const int n0 = blockIdx.x * BN;

    float acc[TM][TN];
    #pragma unroll
    for (int i = 0; i < TM; i++)
        #pragma unroll
        for (int j = 0; j < TN; j++) acc[i][j] = 0.f;

    // preload tile 0
    #pragma unroll
    for (int r = 0; r < AV; r++) {
        int u = tid + r * NT, m = u / KQ, kq = u % KQ;
        float4 a = *(const float4*)&A[(size_t)(m0 + m) * K + kq * 4];
        As[0][kq * 4 + 0][m] = a.x; As[0][kq * 4 + 1][m] = a.y;
        As[0][kq * 4 + 2][m] = a.z; As[0][kq * 4 + 3][m] = a.w;
    }
    #pragma unroll
    for (int r = 0; r < BV; r++) {
        int u = tid + r * NT, kr = u / NQ, nq = u % NQ;
        *(float4*)&Bs[0][kr][nq * 4] = *(const float4*)&B[(size_t)kr * N + n0 + nq * 4];
    }
    __syncthreads();

    const int nk = K / BK;
    float4 pa[AV], pb[BV];

    for (int t = 0; t < nk; t++) {
        const int cur = t & 1;
        if (t + 1 < nk) {
            const int k0 = (t + 1) * BK;
            #pragma unroll
            for (int r = 0; r < AV; r++) {
                int u = tid + r * NT, m = u / KQ, kq = u % KQ;
                pa[r] = *(const float4*)&A[(size_t)(m0 + m) * K + k0 + kq * 4];
            }
            #pragma unroll
            for (int r = 0; r < BV; r++) {
                int u = tid + r * NT, kr = u / NQ, nq = u % NQ;
                pb[r] = *(const float4*)&B[(size_t)(k0 + kr) * N + n0 + nq * 4];
            }
        }
        #pragma unroll
        for (int k = 0; k < BK; k++) {
            float ra[TM], rb[TN];
            if constexpr (TM == 4) {
                float4 t4 = *(const float4*)&As[cur][k][ty * 4];
                ra[0] = t4.x; ra[1] = t4.y; ra[2] = t4.z; ra[3] = t4.w;
            } else {
                float2 t2 = *(const float2*)&As[cur][k][ty * 2];
                ra[0] = t2.x; ra[1] = t2.y;
            }
            {
                float4 t4 = *(const float4*)&Bs[cur][k][tx * 4];
                rb[0] = t4.x; rb[1] = t4.y; rb[2] = t4.z; rb[3] = t4.w;
            }
            #pragma unroll
            for (int i = 0; i < TM; i++)
                #pragma unroll
                for (int j = 0; j < TN; j++) acc[i][j] += ra[i] * rb[j];
        }
        if (t + 1 < nk) {
            const int nb = cur ^ 1;
            #pragma unroll
            for (int r = 0; r < AV; r++) {
                int u = tid + r * NT, m = u / KQ, kq = u % KQ;
                As[nb][kq * 4 + 0][m] = pa[r].x; As[nb][kq * 4 + 1][m] = pa[r].y;
                As[nb][kq * 4 + 2][m] = pa[r].z; As[nb][kq * 4 + 3][m] = pa[r].w;
            }
            #pragma unroll
            for (int r = 0; r < BV; r++) {
                int u = tid + r * NT, kr = u / NQ, nq = u % NQ;
                *(float4*)&Bs[nb][kr][nq * 4] = pb[r];
            }
        }
        __syncthreads();
    }

    // epilogue
    float4 bs4 = *(const float4*)&bias[n0 + tx * 4];
    #pragma unroll
    for (int i = 0; i < TM; i++) {
        const int m = m0 + ty * TM + i;
        float4 o;
        o.x = acc[i][0] + bs4.x; o.y = acc[i][1] + bs4.y;
        o.z = acc[i][2] + bs4.z; o.w = acc[i][3] + bs4.w;
        if (EPI == 0) {
            o.x = fmaxf(o.x, 0.f); o.y = fmaxf(o.y, 0.f);
            o.z = fmaxf(o.z, 0.f); o.w = fmaxf(o.w, 0.f);
        } else {
            float4 rr = *(const float4*)&resid[(size_t)m * N + n0 + tx * 4];
            o.x += rr.x; o.y += rr.y; o.z += rr.z; o.w += rr.w;
        }
        *(float4*)&C[(size_t)m * N + n0 + tx * 4] = o;
    }
}

// ---------------------------------------------------------------------------
// Kernel 3: logits[b][s] = dot(g2[b], lk[b][s]) / sqrt(E)
// grid (4 s-chunks of 250, 256 batches), 1024 threads, 2 rows/warp/iter
// ---------------------------------------------------------------------------
__global__ __launch_bounds__(1024) void logits_kernel(
    const float* __restrict__ g2,
    const float* __restrict__ lk,
    float* __restrict__ out)
{
    __shared__ float gs[Esz];
    const int b    = blockIdx.y;
    const int tid  = threadIdx.x;
    const int wid  = tid >> 5;
    const int lane = tid & 31;

    if (tid < Esz) gs[tid] = g2[b * Esz + tid];
    __syncthreads();

    const float4* g4 = (const float4*)gs;
    const int s0 = blockIdx.x * 250;
    const float rscale = 0.04419417382415922f;  // 1/sqrt(512)

    for (int i = wid * 2; i < 250; i += 64) {
        const int s = s0 + i;
        const float4* r0 = (const float4*)(lk + ((size_t)b * Ssz + s) * Esz);
        const float4* r1 = (const float4*)(lk + ((size_t)b * Ssz + s + 1) * Esz);
        float p0 = 0.f, p1 = 0.f;
        #pragma unroll
        for (int j = 0; j < 4; j++) {
            float4 a0 = r0[j * 32 + lane];
            float4 a1 = r1[j * 32 + lane];
            float4 qv = g4[j * 32 + lane];
            p0 += a0.x * qv.x + a0.y * qv.y + a0.z * qv.z + a0.w * qv.w;
            p1 += a1.x * qv.x + a1.y * qv.y + a1.z * qv.z + a1.w * qv.w;
        }
        #pragma unroll
        for (int o = 16; o; o >>= 1) {
            p0 += __shfl_xor_sync(0xffffffffu, p0, o);
            p1 += __shfl_xor_sync(0xffffffffu, p1, o);
        }
        if (lane == 0) {
            out[(size_t)b * Ssz + s]     = p0 * rscale;
            out[(size_t)b * Ssz + s + 1] = p1 * rscale;
        }
    }
}

// ---------------------------------------------------------------------------
extern "C" void kernel_launch(void* const* d_in, const int* in_sizes, int n_in,
                              void* d_out, int out_size)
{
    const float* query    = (const float*)d_in[0];
    const float* key      = (const float*)d_in[1];
    const float* value    = (const float*)d_in[2];
    const float* logitkey = (const float*)d_in[3];
    const int*   mask     = (const int*)  d_in[4];
    const float* W1       = (const float*)d_in[5];
    const float* b1       = (const float*)d_in[6];
    const float* W2       = (const float*)d_in[7];
    const float* b2       = (const float*)d_in[8];
    float* out            = (float*)d_out;

    float *p_glimpse, *p_T, *p_G2;
    cudaGetSymbolAddress((void**)&p_glimpse, g_glimpse);
    cudaGetSymbolAddress((void**)&p_T, g_T);
    cudaGetSymbolAddress((void**)&p_G2, g_G2);

    attn_kernel<<<dim3(4, Bb), 256>>>(query, key, value, mask, p_glimpse);

    // T = relu(G @ W1 + b1)    M=256, N=2048, K=512
    gemm_kernel<64, 64, 32, 4, 4, 256, 0>
        <<<dim3(DFFsz / 64, Bb / 64), 256>>>(p_glimpse, W1, p_T, b1, nullptr,
                                             Bb, DFFsz, Esz);

    // G2 = T @ W2 + b2 + G     M=256, N=512, K=2048
    gemm_kernel<32, 32, 32, 2, 4, 128, 1>
        <<<dim3(Esz / 32, Bb / 32), 128>>>(p_T, W2, p_G2, b2, p_glimpse,
                                           Bb, Esz, DFFsz);

    logits_kernel<<<dim3(4, Bb), 1024>>>(p_G2, logitkey, out);
}